// round 5
// baseline (speedup 1.0000x reference)
#include <cuda_runtime.h>

// out[b,m] = dot(inputs[b,m,:], W[m,:]) + bias[m]
// B=1024, M=2048, I=128 (fp32). Purely HBM-bound: 1.082 GB traffic.
// One warp computes 8 consecutive rows. All 8 x-row loads (DRAM) are
// front-batched with streaming hint (used once); W rows come from L2
// (W = 1 MB, resident). Reduced sums are parked one-per-lane so the
// warp issues a single coalesced 32B store.

constexpr int B_DIM = 1024;
constexpr int M_DIM = 2048;
constexpr int I_DIM = 128;                  // 32 float4 per row
constexpr int ROWS_PER_WARP = 8;
constexpr int THREADS = 256;                // 8 warps/block
constexpr long long TOTAL_ROWS = (long long)B_DIM * M_DIM;        // 2,097,152
constexpr int ROWS_PER_BLOCK = ROWS_PER_WARP * (THREADS / 32);    // 64
constexpr int GRID = (int)(TOTAL_ROWS / ROWS_PER_BLOCK);          // 32,768

__global__ __launch_bounds__(THREADS)
void diag_linear_kernel(const float4* __restrict__ x,     // [B*M, 32] float4
                        const float4* __restrict__ w,     // [M, 32] float4
                        const float*  __restrict__ bias,  // [M]
                        float*        __restrict__ out)   // [B*M]
{
    const int lane = threadIdx.x & 31;
    const int warp_in_block = threadIdx.x >> 5;
    const long long warp_global = (long long)blockIdx.x * (THREADS / 32) + warp_in_block;
    const long long row0 = warp_global * ROWS_PER_WARP;

    // Front-batch all DRAM loads (8 independent LDG.128.CS in flight per warp).
    float4 a[ROWS_PER_WARP];
#pragma unroll
    for (int r = 0; r < ROWS_PER_WARP; r++) {
        a[r] = __ldcs(&x[(row0 + r) * (I_DIM / 4) + lane]);   // evict-first: used once
    }

    // W rows: L2-resident (1 MB), front-batch too for pipelining.
    float4 ww[ROWS_PER_WARP];
#pragma unroll
    for (int r = 0; r < ROWS_PER_WARP; r++) {
        const int m = (int)((row0 + r) & (M_DIM - 1));
        ww[r] = __ldg(&w[(long long)m * (I_DIM / 4) + lane]);
    }

    float keep = 0.0f;
#pragma unroll
    for (int r = 0; r < ROWS_PER_WARP; r++) {
        float s = fmaf(a[r].x, ww[r].x,
                  fmaf(a[r].y, ww[r].y,
                  fmaf(a[r].z, ww[r].z,
                       a[r].w * ww[r].w)));
#pragma unroll
        for (int off = 16; off; off >>= 1)
            s += __shfl_xor_sync(0xffffffffu, s, off);
        if (lane == r) keep = s;   // park row r's sum on lane r
    }

    // One coalesced 32B store per warp (lanes 0..7), bias added here.
    if (lane < ROWS_PER_WARP) {
        const long long row = row0 + lane;
        const int m = (int)(row & (M_DIM - 1));
        out[row] = keep + __ldg(&bias[m]);
    }
}

extern "C" void kernel_launch(void* const* d_in, const int* in_sizes, int n_in,
                              void* d_out, int out_size)
{
    const float4* x    = (const float4*)d_in[0];  // inputs  [B, M, I]
    const float4* w    = (const float4*)d_in[1];  // Rk_weight [M, I]
    const float*  bias = (const float*)d_in[2];   // bias [M]
    float* out = (float*)d_out;                   // [B, M]

    diag_linear_kernel<<<GRID, THREADS>>>(x, w, bias, out);
}